// round 1
// baseline (speedup 1.0000x reference)
#include <cuda_runtime.h>
#include <math.h>

// Problem constants
#define Bb 4
#define Ss 1024
#define Dd 512
#define Ee 64
#define Hh 8
#define BS (Bb*Ss)      // 4096
#define DH (Dd*Hh)      // 4096

// ---------------- Scratch (device globals; no allocation allowed) ----------------
__device__ float g_Q[Hh*Bb*Ss*Ee];      // [H,B,S,E]
__device__ float g_K[Hh*Bb*Ss*Ee];      // [H,B,S,E]
__device__ float g_V[Hh*Bb*Ss*Dd];      // [H,B,S,D]
__device__ float g_S[(long)Hh*Bb*Ss*Ss];// [H,B,S,S] scores / attn probs (128MB)
__device__ float g_a[Bb*Ss*DH];         // [B,S,D*H] interleaved heads
__device__ float g_attn[Bb*Ss*Dd];      // attn_out
__device__ float g_x1[Bb*Ss*Dd];        // after LN1
__device__ float g_h1[Bb*Ss*Dd];        // after ELU(W1)
__device__ float g_f[Bb*Ss*Dd];         // after W2

// ---------------- Generic tiled SGEMM ----------------
// C = alpha * A @ op(B)  [+ bias] [+ ELU]
// Batched over blockIdx.z with linear strides sA,sB,sC.
// TRANSB: B is [N,K] row-major (C[m,n] = sum_k A[m,k]*B[n,k]).
// ACT: 0 none, 1 +bias, 2 +bias then ELU.
// INTERLEAVE: z = h*Bb + b; C base = C + b*sC + h, column stride = Hh
//             (writes O[h,b,s,d] directly into a[b,s,d*H+h]).
template<bool TRANSB, int ACT, bool INTERLEAVE>
__global__ __launch_bounds__(256)
void sgemm(const float* __restrict__ A, const float* __restrict__ B,
           float* __restrict__ C, const float* __restrict__ bias,
           int M, int N, int K, int lda, int ldb, int ldc,
           float alpha, long sA, long sB, long sC)
{
    const int BM = 64, BN = 64, BK = 16;
    __shared__ float As[BK][BM + 1];
    __shared__ float Bs[BK][BN + 1];

    int z = blockIdx.z;
    const float* Ab = A + (long)z * sA;
    const float* Bp = B + (long)z * sB;
    float* Cb;
    const int cstride = INTERLEAVE ? Hh : 1;
    if (INTERLEAVE) {
        int h = z / Bb;
        int b = z % Bb;
        Cb = C + (long)b * sC + h;
    } else {
        Cb = C + (long)z * sC;
    }

    int tid = threadIdx.x;         // 256 threads
    int tx = tid & 15, ty = tid >> 4;
    int row0 = blockIdx.y * BM;
    int col0 = blockIdx.x * BN;

    float acc[4][4] = {};

    for (int k0 = 0; k0 < K; k0 += BK) {
        // Load A tile: BM x BK (row-major source, coalesced on k)
        #pragma unroll
        for (int i = 0; i < 4; i++) {
            int e = tid + i * 256;
            int m = e / BK, kk = e % BK;
            As[kk][m] = Ab[(long)(row0 + m) * lda + (k0 + kk)];
        }
        // Load B tile
        #pragma unroll
        for (int i = 0; i < 4; i++) {
            int e = tid + i * 256;
            if (!TRANSB) {
                int kk = e / BN, n = e % BN;
                Bs[kk][n] = Bp[(long)(k0 + kk) * ldb + (col0 + n)];
            } else {
                int n = e / BK, kk = e % BK;
                Bs[kk][n] = Bp[(long)(col0 + n) * ldb + (k0 + kk)];
            }
        }
        __syncthreads();

        #pragma unroll
        for (int kk = 0; kk < BK; kk++) {
            float a[4], b[4];
            #pragma unroll
            for (int i = 0; i < 4; i++) a[i] = As[kk][ty * 4 + i];
            #pragma unroll
            for (int j = 0; j < 4; j++) b[j] = Bs[kk][tx * 4 + j];
            #pragma unroll
            for (int i = 0; i < 4; i++)
                #pragma unroll
                for (int j = 0; j < 4; j++)
                    acc[i][j] = fmaf(a[i], b[j], acc[i][j]);
        }
        __syncthreads();
    }

    #pragma unroll
    for (int i = 0; i < 4; i++) {
        int m = row0 + ty * 4 + i;
        #pragma unroll
        for (int j = 0; j < 4; j++) {
            int n = col0 + tx * 4 + j;
            float v = acc[i][j] * alpha;
            if (ACT >= 1) v += bias[n];
            if (ACT == 2) v = v > 0.f ? v : expm1f(v);
            Cb[(long)m * ldc + (long)n * cstride] = v;
        }
    }
}

// ---------------- Row softmax (in place), ncols = 1024 ----------------
__global__ __launch_bounds__(256)
void softmax_rows(float* __restrict__ S)
{
    const int NC = Ss;
    float* p = S + (long)blockIdx.x * NC;
    int tid = threadIdx.x;
    __shared__ float red[256];

    float m = -1e30f;
    #pragma unroll
    for (int c = tid; c < NC; c += 256) m = fmaxf(m, p[c]);
    red[tid] = m; __syncthreads();
    for (int s = 128; s > 0; s >>= 1) {
        if (tid < s) red[tid] = fmaxf(red[tid], red[tid + s]);
        __syncthreads();
    }
    m = red[0]; __syncthreads();

    float sum = 0.f;
    #pragma unroll
    for (int c = tid; c < NC; c += 256) {
        float e = expf(p[c] - m);
        p[c] = e;
        sum += e;
    }
    red[tid] = sum; __syncthreads();
    for (int s = 128; s > 0; s >>= 1) {
        if (tid < s) red[tid] += red[tid + s];
        __syncthreads();
    }
    float inv = 1.f / red[0];
    #pragma unroll
    for (int c = tid; c < NC; c += 256) p[c] *= inv;
}

// ---------------- Fused residual + LayerNorm, ncols = 512 ----------------
__global__ __launch_bounds__(256)
void residual_ln(const float* __restrict__ X, const float* __restrict__ Y,
                 const float* __restrict__ g, const float* __restrict__ be,
                 float* __restrict__ out)
{
    const int NC = Dd;
    long row = blockIdx.x;
    const float* x = X + row * NC;
    const float* y = Y + row * NC;
    float* o = out + row * NC;
    int tid = threadIdx.x;
    __shared__ float red[256];

    float v0 = x[tid] + y[tid];
    float v1 = x[tid + 256] + y[tid + 256];

    red[tid] = v0 + v1; __syncthreads();
    for (int s = 128; s > 0; s >>= 1) {
        if (tid < s) red[tid] += red[tid + s];
        __syncthreads();
    }
    float mu = red[0] * (1.f / NC); __syncthreads();

    float d0 = v0 - mu, d1 = v1 - mu;
    red[tid] = d0 * d0 + d1 * d1; __syncthreads();
    for (int s = 128; s > 0; s >>= 1) {
        if (tid < s) red[tid] += red[tid + s];
        __syncthreads();
    }
    float rstd = rsqrtf(red[0] * (1.f / NC) + 1e-5f);

    o[tid]       = d0 * rstd * g[tid]       + be[tid];
    o[tid + 256] = d1 * rstd * g[tid + 256] + be[tid + 256];
}

// ---------------- Launch ----------------
extern "C" void kernel_launch(void* const* d_in, const int* in_sizes, int n_in,
                              void* d_out, int out_size)
{
    const float* x  = (const float*)d_in[0];
    const float* Wq = (const float*)d_in[1];
    const float* Wk = (const float*)d_in[2];
    const float* Wv = (const float*)d_in[3];
    const float* Wo = (const float*)d_in[4];
    const float* W1 = (const float*)d_in[5];
    const float* b1 = (const float*)d_in[6];
    const float* W2 = (const float*)d_in[7];
    const float* b2 = (const float*)d_in[8];
    const float* g1 = (const float*)d_in[9];
    const float* be1= (const float*)d_in[10];
    const float* g2 = (const float*)d_in[11];
    const float* be2= (const float*)d_in[12];
    float* out = (float*)d_out;

    float *Q, *Kp, *V, *Sc, *a, *attn, *x1, *h1, *f;
    cudaGetSymbolAddress((void**)&Q,    g_Q);
    cudaGetSymbolAddress((void**)&Kp,   g_K);
    cudaGetSymbolAddress((void**)&V,    g_V);
    cudaGetSymbolAddress((void**)&Sc,   g_S);
    cudaGetSymbolAddress((void**)&a,    g_a);
    cudaGetSymbolAddress((void**)&attn, g_attn);
    cudaGetSymbolAddress((void**)&x1,   g_x1);
    cudaGetSymbolAddress((void**)&h1,   g_h1);
    cudaGetSymbolAddress((void**)&f,    g_f);

    // 1. Q = x @ Wq[h]   [4096,512]x[512,64] per head
    sgemm<false,0,false><<<dim3(1, 64, Hh), 256>>>(
        x, Wq, Q, nullptr, BS, Ee, Dd, Dd, Ee, Ee, 1.f,
        0L, (long)Dd*Ee, (long)Bb*Ss*Ee);
    // 2. K = x @ Wk[h]
    sgemm<false,0,false><<<dim3(1, 64, Hh), 256>>>(
        x, Wk, Kp, nullptr, BS, Ee, Dd, Dd, Ee, Ee, 1.f,
        0L, (long)Dd*Ee, (long)Bb*Ss*Ee);
    // 3. V = x @ Wv[h]   [4096,512]x[512,512] per head
    sgemm<false,0,false><<<dim3(8, 64, Hh), 256>>>(
        x, Wv, V, nullptr, BS, Dd, Dd, Dd, Dd, Dd, 1.f,
        0L, (long)Dd*Dd, (long)Bb*Ss*Dd);
    // 4. scores = Q @ K^T * 1/sqrt(E)   per (h,b): [1024,64]x[64,1024]
    sgemm<true,0,false><<<dim3(16, 16, Hh*Bb), 256>>>(
        Q, Kp, Sc, nullptr, Ss, Ss, Ee, Ee, Ee, Ss, 0.125f,
        (long)Ss*Ee, (long)Ss*Ee, (long)Ss*Ss);
    // 5. softmax rows
    softmax_rows<<<Hh*Bb*Ss, 256>>>(Sc);
    // 6. O = A @ V, stored interleaved into a[b,s,d*H+h]   per (h,b): [1024,1024]x[1024,512]
    sgemm<false,0,true><<<dim3(8, 16, Hh*Bb), 256>>>(
        Sc, V, a, nullptr, Ss, Dd, Ss, Ss, Dd, DH, 1.f,
        (long)Ss*Ss, (long)Ss*Dd, (long)Ss*DH);
    // 7. attn = a @ Wo   [4096,4096]x[4096,512]
    sgemm<false,0,false><<<dim3(8, 64, 1), 256>>>(
        a, Wo, attn, nullptr, BS, Dd, DH, DH, Dd, Dd, 1.f, 0L, 0L, 0L);
    // 8. x1 = LN(x + attn)
    residual_ln<<<BS, 256>>>(x, attn, g1, be1, x1);
    // 9. h1 = ELU(x1 @ W1 + b1)
    sgemm<false,2,false><<<dim3(8, 64, 1), 256>>>(
        x1, W1, h1, b1, BS, Dd, Dd, Dd, Dd, Dd, 1.f, 0L, 0L, 0L);
    // 10. f = h1 @ W2 + b2
    sgemm<false,1,false><<<dim3(8, 64, 1), 256>>>(
        h1, W2, f, b2, BS, Dd, Dd, Dd, Dd, Dd, 1.f, 0L, 0L, 0L);
    // 11. out = LN(x1 + f)
    residual_ln<<<BS, 256>>>(x1, f, g2, be2, out);
}

// round 4
// speedup vs baseline: 2.2781x; 2.2781x over previous
#include <cuda_runtime.h>
#include <mma.h>
#include <math.h>

using namespace nvcuda;

// Problem constants
#define Bb 4
#define Ss 1024
#define Dd 512
#define Ee 64
#define Hh 8
#define BS (Bb*Ss)      // 4096
#define DH (Dd*Hh)      // 4096

// ---------------- Scratch (device globals; no allocation allowed) ----------------
__device__ float g_Q[Hh*Bb*Ss*Ee];      // [H,B,S,E] (pre-scaled by 1/sqrt(E))
__device__ float g_K[Hh*Bb*Ss*Ee];      // [H,B,S,E]
__device__ float g_V[Hh*Bb*Ss*Dd];      // [H,B,S,D]
__device__ float g_S[(long)Hh*Bb*Ss*Ss];// [H,B,S,S] scores / probs (128MB)
__device__ float g_O[Hh*Bb*Ss*Dd];      // [H,B,S,D] attention output (pre-Wo)
__device__ float g_attn[Bb*Ss*Dd];
__device__ float g_x1[Bb*Ss*Dd];
__device__ float g_h1[Bb*Ss*Dd];
__device__ float g_f[Bb*Ss*Dd];

// ---------------- WMMA tf32 GEMM ----------------
// C = alpha * A @ op(B) [+bias] [+ELU], batched over blockIdx.z.
// TRANSB: B is [N,K] row-major.
// KPERM (Wo GEMM): k = h*512 + d;
//   A element (m,k) = O[h, m, d]      -> A + h*BS*Dd + m*512 + d
//   B element (k,n) = Wo[d*8 + h, n]  -> B + (d*8+h)*512 + n
// Block 128x64, BK=16, double buffered; 8 warps of 32x32 (2x2 m16n16k8 tiles).
//
// SMEM pool (floats), per stage 4608:
//   As: [128][24]  (row-major m x k, ld=24)
//   Bs: !TRANSB -> [16][72] (row-major k x n, ld=72)
//        TRANSB -> [64][24] (col-major view: element (k,n) at n*24+k, ld=24)
// Epilogue reuses the pool as 8 x [32][32] per-warp scratch (8192 <= 9216).
#define APAD 24
#define BROW 72
#define STAGE 4608

template<bool TRANSB, int ACT, bool KPERM>
__global__ __launch_bounds__(256, 2)
void tgemm(const float* __restrict__ A, const float* __restrict__ B,
           float* __restrict__ C, const float* __restrict__ bias,
           int M, int N, int K, int lda, int ldb, int ldc,
           float alpha, long sA, long sB, long sC)
{
    const int BK = 16;
    __shared__ __align__(32) float pool[2 * STAGE];

    const int z = blockIdx.z;
    const float* Ab = A + (long)z * sA;
    const float* Bp = B + (long)z * sB;
    float* Cb = C + (long)z * sC;

    const int tid = threadIdx.x;
    const int wid = tid >> 5, lane = tid & 31;
    const int wm = (wid & 3) * 32, wn = (wid >> 2) * 32;
    const int row0 = blockIdx.y * 128, col0 = blockIdx.x * 64;

    wmma::fragment<wmma::accumulator, 16, 16, 8, float> acc[2][2];
    #pragma unroll
    for (int i = 0; i < 2; i++)
        #pragma unroll
        for (int j = 0; j < 2; j++)
            wmma::fill_fragment(acc[i][j], 0.0f);

    float4 ra[2], rb;

    auto ldg = [&](int k0) {
        #pragma unroll
        for (int i = 0; i < 2; i++) {
            int m = row0 + (tid >> 2) + i * 64;
            int k = k0 + 4 * (tid & 3);
            const float* s;
            if (KPERM) s = A + (long)(k >> 9) * ((long)BS * Dd) + (long)m * 512 + (k & 511);
            else       s = Ab + (long)m * lda + k;
            ra[i] = *(const float4*)s;
        }
        if (TRANSB) {
            int n = col0 + (tid >> 2), k = k0 + 4 * (tid & 3);
            rb = *(const float4*)(Bp + (long)n * ldb + k);
        } else {
            int k = k0 + (tid >> 4), n = col0 + 4 * (tid & 15);
            const float* s;
            if (KPERM) s = B + ((long)(k & 511) * 8 + (k >> 9)) * 512 + n;
            else       s = Bp + (long)k * ldb + n;
            rb = *(const float4*)s;
        }
    };

    auto sts = [&](int st) {
        float* As_ = pool + st * STAGE;
        float* Bs_ = pool + st * STAGE + 128 * APAD;
        #pragma unroll
        for (int i = 0; i < 2; i++) {
            int m = (tid >> 2) + i * 64, kq = 4 * (tid & 3);
            float* d = As_ + m * APAD + kq;
            d[0] = wmma::__float_to_tf32(ra[i].x);
            d[1] = wmma::__float_to_tf32(ra[i].y);
            d[2] = wmma::__float_to_tf32(ra[i].z);
            d[3] = wmma::__float_to_tf32(ra[i].w);
        }
        if (TRANSB) {
            int n = tid >> 2, kq = 4 * (tid & 3);
            float* d = Bs_ + n * APAD + kq;
            d[0] = wmma::__float_to_tf32(rb.x);
            d[1] = wmma::__float_to_tf32(rb.y);
            d[2] = wmma::__float_to_tf32(rb.z);
            d[3] = wmma::__float_to_tf32(rb.w);
        } else {
            int kk = tid >> 4, n4 = 4 * (tid & 15);
            float* d = Bs_ + kk * BROW + n4;
            d[0] = wmma::__float_to_tf32(rb.x);
            d[1] = wmma::__float_to_tf32(rb.y);
            d[2] = wmma::__float_to_tf32(rb.z);
            d[3] = wmma::__float_to_tf32(rb.w);
        }
    };

    auto comp = [&](int st) {
        const float* As_ = pool + st * STAGE;
        const float* Bs_ = pool + st * STAGE + 128 * APAD;
        #pragma unroll
        for (int kb = 0; kb < BK; kb += 8) {
            wmma::fragment<wmma::matrix_a, 16, 16, 8, wmma::precision::tf32, wmma::row_major> af[2];
            #pragma unroll
            for (int mb = 0; mb < 2; mb++)
                wmma::load_matrix_sync(af[mb], As_ + (wm + mb * 16) * APAD + kb, APAD);
            #pragma unroll
            for (int nb = 0; nb < 2; nb++) {
                if (TRANSB) {
                    wmma::fragment<wmma::matrix_b, 16, 16, 8, wmma::precision::tf32, wmma::col_major> bf;
                    wmma::load_matrix_sync(bf, Bs_ + (wn + nb * 16) * APAD + kb, APAD);
                    #pragma unroll
                    for (int mb = 0; mb < 2; mb++)
                        wmma::mma_sync(acc[mb][nb], af[mb], bf, acc[mb][nb]);
                } else {
                    wmma::fragment<wmma::matrix_b, 16, 16, 8, wmma::precision::tf32, wmma::row_major> bf;
                    wmma::load_matrix_sync(bf, Bs_ + kb * BROW + wn + nb * 16, BROW);
                    #pragma unroll
                    for (int mb = 0; mb < 2; mb++)
                        wmma::mma_sync(acc[mb][nb], af[mb], bf, acc[mb][nb]);
                }
            }
        }
    };

    ldg(0); sts(0); __syncthreads();
    const int nk = K / BK;
    int st = 0;
    for (int kt = 1; kt < nk; kt++) {
        ldg(kt * BK);
        comp(st);
        sts(st ^ 1);
        __syncthreads();
        st ^= 1;
    }
    comp(st);
    __syncthreads();   // all warps done reading smem before reuse as scratch

    // Epilogue: stage accumulators through smem for explicit (row,col) indexing.
    float* scratch = pool + wid * 1024;   // [32][32] per warp
    #pragma unroll
    for (int mb = 0; mb < 2; mb++)
        #pragma unroll
        for (int nb = 0; nb < 2; nb++)
            wmma::store_matrix_sync(scratch + mb * 16 * 32 + nb * 16, acc[mb][nb], 32, wmma::mem_row_major);
    __syncwarp();

    #pragma unroll
    for (int it = 0; it < 8; it++) {
        int r  = it * 4 + (lane >> 3);
        int c4 = (lane & 7) * 4;
        float4 v = *(float4*)(scratch + r * 32 + c4);
        int m = row0 + wm + r;
        int n = col0 + wn + c4;
        v.x *= alpha; v.y *= alpha; v.z *= alpha; v.w *= alpha;
        if (ACT >= 1) {
            v.x += bias[n];     v.y += bias[n + 1];
            v.z += bias[n + 2]; v.w += bias[n + 3];
        }
        if (ACT == 2) {
            v.x = v.x > 0.f ? v.x : expm1f(v.x);
            v.y = v.y > 0.f ? v.y : expm1f(v.y);
            v.z = v.z > 0.f ? v.z : expm1f(v.z);
            v.w = v.w > 0.f ? v.w : expm1f(v.w);
        }
        *(float4*)&Cb[(long)m * ldc + n] = v;
    }
}

// ---------------- Row softmax, 1024 cols, one read + one write ----------------
__global__ __launch_bounds__(256)
void softmax_rows(float* __restrict__ S)
{
    const int tid = threadIdx.x;
    float4* p = (float4*)S + (long)blockIdx.x * 256 + tid;
    float4 v = *p;

    __shared__ float sred[8];
    float m = fmaxf(fmaxf(v.x, v.y), fmaxf(v.z, v.w));
    #pragma unroll
    for (int o = 16; o; o >>= 1) m = fmaxf(m, __shfl_xor_sync(0xffffffffu, m, o));
    if ((tid & 31) == 0) sred[tid >> 5] = m;
    __syncthreads();
    float mm = sred[0];
    #pragma unroll
    for (int i = 1; i < 8; i++) mm = fmaxf(mm, sred[i]);

    v.x = expf(v.x - mm); v.y = expf(v.y - mm);
    v.z = expf(v.z - mm); v.w = expf(v.w - mm);
    float s = v.x + v.y + v.z + v.w;
    #pragma unroll
    for (int o = 16; o; o >>= 1) s += __shfl_xor_sync(0xffffffffu, s, o);
    __syncthreads();
    if ((tid & 31) == 0) sred[tid >> 5] = s;
    __syncthreads();
    float tot = sred[0];
    #pragma unroll
    for (int i = 1; i < 8; i++) tot += sred[i];
    float inv = 1.f / tot;

    v.x *= inv; v.y *= inv; v.z *= inv; v.w *= inv;
    *p = v;
}

// ---------------- Fused residual + LayerNorm, 512 cols ----------------
__global__ __launch_bounds__(256)
void residual_ln(const float* __restrict__ X, const float* __restrict__ Y,
                 const float* __restrict__ g, const float* __restrict__ be,
                 float* __restrict__ out)
{
    const int NC = Dd;
    long row = blockIdx.x;
    const float* x = X + row * NC;
    const float* y = Y + row * NC;
    float* o = out + row * NC;
    int tid = threadIdx.x;
    __shared__ float red[256];

    float v0 = x[tid] + y[tid];
    float v1 = x[tid + 256] + y[tid + 256];

    red[tid] = v0 + v1; __syncthreads();
    for (int s = 128; s > 0; s >>= 1) {
        if (tid < s) red[tid] += red[tid + s];
        __syncthreads();
    }
    float mu = red[0] * (1.f / NC); __syncthreads();

    float d0 = v0 - mu, d1 = v1 - mu;
    red[tid] = d0 * d0 + d1 * d1; __syncthreads();
    for (int s = 128; s > 0; s >>= 1) {
        if (tid < s) red[tid] += red[tid + s];
        __syncthreads();
    }
    float rstd = rsqrtf(red[0] * (1.f / NC) + 1e-5f);

    o[tid]       = d0 * rstd * g[tid]       + be[tid];
    o[tid + 256] = d1 * rstd * g[tid + 256] + be[tid + 256];
}

// ---------------- Launch ----------------
extern "C" void kernel_launch(void* const* d_in, const int* in_sizes, int n_in,
                              void* d_out, int out_size)
{
    const float* x  = (const float*)d_in[0];
    const float* Wq = (const float*)d_in[1];
    const float* Wk = (const float*)d_in[2];
    const float* Wv = (const float*)d_in[3];
    const float* Wo = (const float*)d_in[4];
    const float* W1 = (const float*)d_in[5];
    const float* b1 = (const float*)d_in[6];
    const float* W2 = (const float*)d_in[7];
    const float* b2 = (const float*)d_in[8];
    const float* g1 = (const float*)d_in[9];
    const float* be1= (const float*)d_in[10];
    const float* g2 = (const float*)d_in[11];
    const float* be2= (const float*)d_in[12];
    float* out = (float*)d_out;

    float *Q, *Kp, *V, *Sc, *O, *attn, *x1, *h1, *f;
    cudaGetSymbolAddress((void**)&Q,    g_Q);
    cudaGetSymbolAddress((void**)&Kp,   g_K);
    cudaGetSymbolAddress((void**)&V,    g_V);
    cudaGetSymbolAddress((void**)&Sc,   g_S);
    cudaGetSymbolAddress((void**)&O,    g_O);
    cudaGetSymbolAddress((void**)&attn, g_attn);
    cudaGetSymbolAddress((void**)&x1,   g_x1);
    cudaGetSymbolAddress((void**)&h1,   g_h1);
    cudaGetSymbolAddress((void**)&f,    g_f);

    // 1. Q = (x @ Wq[h]) * 1/sqrt(E)    [4096,512]x[512,64] per head
    tgemm<false,0,false><<<dim3(1, 32, Hh), 256>>>(
        x, Wq, Q, nullptr, BS, Ee, Dd, Dd, Ee, Ee, 0.125f,
        0L, (long)Dd*Ee, (long)Bb*Ss*Ee);
    // 2. K = x @ Wk[h]
    tgemm<false,0,false><<<dim3(1, 32, Hh), 256>>>(
        x, Wk, Kp, nullptr, BS, Ee, Dd, Dd, Ee, Ee, 1.f,
        0L, (long)Dd*Ee, (long)Bb*Ss*Ee);
    // 3. V = x @ Wv[h]    [4096,512]x[512,512] per head
    tgemm<false,0,false><<<dim3(8, 32, Hh), 256>>>(
        x, Wv, V, nullptr, BS, Dd, Dd, Dd, Dd, Dd, 1.f,
        0L, (long)Dd*Dd, (long)Bb*Ss*Dd);
    // 4. scores = Q @ K^T    per (h,b): [1024,64]x[64,1024]
    tgemm<true,0,false><<<dim3(16, 8, Hh*Bb), 256>>>(
        Q, Kp, Sc, nullptr, Ss, Ss, Ee, Ee, Ee, Ss, 1.f,
        (long)Ss*Ee, (long)Ss*Ee, (long)Ss*Ss);
    // 5. softmax rows
    softmax_rows<<<Hh*Bb*Ss, 256>>>(Sc);
    // 6. O[h,b] = A @ V     per (h,b): [1024,1024]x[1024,512], contiguous store
    tgemm<false,0,false><<<dim3(8, 8, Hh*Bb), 256>>>(
        Sc, V, O, nullptr, Ss, Dd, Ss, Ss, Dd, Dd, 1.f,
        (long)Ss*Ss, (long)Ss*Dd, (long)Ss*Dd);
    // 7. attn = a @ Wo with k=(h,d) permutation folded into the loads
    tgemm<false,0,true><<<dim3(8, 32, 1), 256>>>(
        O, Wo, attn, nullptr, BS, Dd, DH, Dd, Dd, Dd, 1.f, 0L, 0L, 0L);
    // 8. x1 = LN(x + attn)
    residual_ln<<<BS, 256>>>(x, attn, g1, be1, x1);
    // 9. h1 = ELU(x1 @ W1 + b1)
    tgemm<false,2,false><<<dim3(8, 32, 1), 256>>>(
        x1, W1, h1, b1, BS, Dd, Dd, Dd, Dd, Dd, 1.f, 0L, 0L, 0L);
    // 10. f = h1 @ W2 + b2
    tgemm<false,1,false><<<dim3(8, 32, 1), 256>>>(
        h1, W2, f, b2, BS, Dd, Dd, Dd, Dd, Dd, 1.f, 0L, 0L, 0L);
    // 11. out = LN(x1 + f)
    residual_ln<<<BS, 256>>>(x1, f, g2, be2, out);
}

// round 5
// speedup vs baseline: 2.3525x; 1.0327x over previous
#include <cuda_runtime.h>
#include <mma.h>
#include <math.h>

using namespace nvcuda;

// Problem constants
#define Bb 4
#define Ss 1024
#define Dd 512
#define Ee 64
#define Hh 8
#define BS (Bb*Ss)      // 4096
#define DH (Dd*Hh)      // 4096

// ---------------- Scratch (device globals; no allocation allowed) ----------------
__device__ float g_Wqk[Hh*Dd*128];      // packed [H][512][128] = Wq | Wk
__device__ float g_QK[Hh*BS*128];       // [H,B,S,128]: Q|K per row
__device__ float g_V[Hh*Bb*Ss*Dd];      // [H,B,S,D]
__device__ float g_S[(long)Hh*Bb*Ss*Ss];// [H,B,S,S] unnormalized probs P=exp(s)
__device__ float g_lpart[Hh*Bb*8*Ss];   // [z][xtile(8)][row] partial row sums
__device__ float g_O[Hh*Bb*Ss*Dd];      // [H,B,S,D] attention output (pre-Wo)
__device__ float g_attn[Bb*Ss*Dd];
__device__ float g_x1[Bb*Ss*Dd];
__device__ float g_h1[Bb*Ss*Dd];
__device__ float g_f[Bb*Ss*Dd];

// ---------------- WMMA tf32 GEMM ----------------
// C = alpha * A @ op(B) [+bias / +ELU / exp+rowsum], batched over blockIdx.z.
// TRANSB: B is [N,K] row-major.
// KPERM (Wo GEMM): k = h*512 + d;
//   A element (m,k) = O[h, m, d]      -> A + h*BS*Dd + m*512 + d
//   B element (k,n) = Wo[d*8 + h, n]  -> B + (d*8+h)*512 + n
// ACT: 0 none, 1 +bias, 2 +bias+ELU, 3 exp(alpha*v) + per-row partial sums -> lpart
// DIVROW: divide each output row by sum of 8 lpart partials (softmax denom).
// Block 128x128, BK=16, 2-stage register prefetch; 8 warps of 64x32 (4x2 m16n16k8).
//
// SMEM pool (floats), per stage 5120:
//   As: [128][20] row-major, ld=20
//   Bs: TRANSB -> [128][20] "col-major" (element (k,n) at n*20+k), ld=20
//       else   -> [16][132] row-major, ld=132
// Epilogue reuses pool as 8 x [16][40] per-warp scratch.
#define STAGE 5120

template<bool TRANSB, int ACT, bool KPERM, bool DIVROW>
__global__ __launch_bounds__(256, 2)
void tgemm(const float* __restrict__ A, const float* __restrict__ B,
           float* __restrict__ C, const float* __restrict__ bias,
           float* __restrict__ lpart,
           int M, int N, int K, int lda, int ldb, int ldc,
           float alpha, long sA, long sB, long sC)
{
    const int BK = 16;
    __shared__ __align__(128) float pool[2 * STAGE];
    __shared__ float sm_l[4][128];

    const int z = blockIdx.z;
    const float* Ab = A + (long)z * sA;
    const float* Bp = B + (long)z * sB;
    float* Cb = C + (long)z * sC;

    const int tid = threadIdx.x;
    const int wid = tid >> 5, lane = tid & 31;
    const int wm = (wid & 1) * 64, wn = (wid >> 1) * 32;
    const int row0 = blockIdx.y * 128, col0 = blockIdx.x * 128;

    wmma::fragment<wmma::accumulator, 16, 16, 8, float> acc[4][2];
    #pragma unroll
    for (int i = 0; i < 4; i++)
        #pragma unroll
        for (int j = 0; j < 2; j++)
            wmma::fill_fragment(acc[i][j], 0.0f);

    float4 ra[2], rb[2];

    auto ldg = [&](int k0) {
        #pragma unroll
        for (int i = 0; i < 2; i++) {
            int m = row0 + (tid >> 2) + i * 64;
            int k = k0 + 4 * (tid & 3);
            const float* s;
            if (KPERM) s = A + (long)(k >> 9) * ((long)BS * Dd) + (long)m * 512 + (k & 511);
            else       s = Ab + (long)m * lda + k;
            ra[i] = *(const float4*)s;
        }
        if (TRANSB) {
            #pragma unroll
            for (int i = 0; i < 2; i++) {
                int n = col0 + (tid >> 2) + i * 64;
                int k = k0 + 4 * (tid & 3);
                rb[i] = *(const float4*)(Bp + (long)n * ldb + k);
            }
        } else {
            #pragma unroll
            for (int i = 0; i < 2; i++) {
                int k = k0 + (tid >> 5) + i * 8;
                int n = col0 + 4 * (tid & 31);
                const float* s;
                if (KPERM) s = B + ((long)(k & 511) * 8 + (k >> 9)) * 512 + n;
                else       s = Bp + (long)k * ldb + n;
                rb[i] = *(const float4*)s;
            }
        }
    };

    auto sts = [&](int st) {
        float* As_ = pool + st * STAGE;
        float* Bs_ = pool + st * STAGE + 2560;
        #pragma unroll
        for (int i = 0; i < 2; i++) {
            int m = (tid >> 2) + i * 64, kq = 4 * (tid & 3);
            float* d = As_ + m * 20 + kq;
            d[0] = wmma::__float_to_tf32(ra[i].x);
            d[1] = wmma::__float_to_tf32(ra[i].y);
            d[2] = wmma::__float_to_tf32(ra[i].z);
            d[3] = wmma::__float_to_tf32(ra[i].w);
        }
        if (TRANSB) {
            #pragma unroll
            for (int i = 0; i < 2; i++) {
                int n = (tid >> 2) + i * 64, kq = 4 * (tid & 3);
                float* d = Bs_ + n * 20 + kq;
                d[0] = wmma::__float_to_tf32(rb[i].x);
                d[1] = wmma::__float_to_tf32(rb[i].y);
                d[2] = wmma::__float_to_tf32(rb[i].z);
                d[3] = wmma::__float_to_tf32(rb[i].w);
            }
        } else {
            #pragma unroll
            for (int i = 0; i < 2; i++) {
                int kk = (tid >> 5) + i * 8, n4 = 4 * (tid & 31);
                float* d = Bs_ + kk * 132 + n4;
                d[0] = wmma::__float_to_tf32(rb[i].x);
                d[1] = wmma::__float_to_tf32(rb[i].y);
                d[2] = wmma::__float_to_tf32(rb[i].z);
                d[3] = wmma::__float_to_tf32(rb[i].w);
            }
        }
    };

    auto comp = [&](int st) {
        const float* As_ = pool + st * STAGE;
        const float* Bs_ = pool + st * STAGE + 2560;
        #pragma unroll
        for (int kb = 0; kb < BK; kb += 8) {
            wmma::fragment<wmma::matrix_a, 16, 16, 8, wmma::precision::tf32, wmma::row_major> af[4];
            #pragma unroll
            for (int mb = 0; mb < 4; mb++)
                wmma::load_matrix_sync(af[mb], As_ + (wm + mb * 16) * 20 + kb, 20);
            #pragma unroll
            for (int nb = 0; nb < 2; nb++) {
                if (TRANSB) {
                    wmma::fragment<wmma::matrix_b, 16, 16, 8, wmma::precision::tf32, wmma::col_major> bf;
                    wmma::load_matrix_sync(bf, Bs_ + (wn + nb * 16) * 20 + kb, 20);
                    #pragma unroll
                    for (int mb = 0; mb < 4; mb++)
                        wmma::mma_sync(acc[mb][nb], af[mb], bf, acc[mb][nb]);
                } else {
                    wmma::fragment<wmma::matrix_b, 16, 16, 8, wmma::precision::tf32, wmma::row_major> bf;
                    wmma::load_matrix_sync(bf, Bs_ + kb * 132 + wn + nb * 16, 132);
                    #pragma unroll
                    for (int mb = 0; mb < 4; mb++)
                        wmma::mma_sync(acc[mb][nb], af[mb], bf, acc[mb][nb]);
                }
            }
        }
    };

    ldg(0); sts(0); __syncthreads();
    const int nk = K / BK;
    int st = 0;
    for (int kt = 1; kt < nk; kt++) {
        ldg(kt * BK);
        comp(st);
        sts(st ^ 1);
        __syncthreads();
        st ^= 1;
    }
    comp(st);
    __syncthreads();   // done reading smem; reuse as epilogue scratch

    // Epilogue: stage 16x32 warp slabs through smem for explicit (row,col) math.
    float* scratch = pool + wid * 640;   // [16][40]
    const int r = lane >> 1, chalf = (lane & 1) * 16;

    #pragma unroll
    for (int mb = 0; mb < 4; mb++) {
        wmma::store_matrix_sync(scratch,      acc[mb][0], 40, wmma::mem_row_major);
        wmma::store_matrix_sync(scratch + 16, acc[mb][1], 40, wmma::mem_row_major);
        __syncwarp();

        const int m = row0 + wm + mb * 16 + r;
        float inv = 1.0f;
        if (DIVROW) {
            float ls = 0.f;
            #pragma unroll
            for (int j = 0; j < 8; j++) ls += lpart[(long)z * 8192 + j * 1024 + m];
            inv = 1.0f / ls;
        }
        float rs = 0.f;
        #pragma unroll
        for (int it = 0; it < 4; it++) {
            int c = chalf + it * 4;
            float4 v = *(float4*)(scratch + r * 40 + c);
            int n = col0 + wn + c;
            v.x *= alpha; v.y *= alpha; v.z *= alpha; v.w *= alpha;
            if (ACT == 1 || ACT == 2) {
                v.x += bias[n];     v.y += bias[n + 1];
                v.z += bias[n + 2]; v.w += bias[n + 3];
            }
            if (ACT == 2) {
                v.x = v.x > 0.f ? v.x : expm1f(v.x);
                v.y = v.y > 0.f ? v.y : expm1f(v.y);
                v.z = v.z > 0.f ? v.z : expm1f(v.z);
                v.w = v.w > 0.f ? v.w : expm1f(v.w);
            }
            if (ACT == 3) {
                v.x = expf(v.x); v.y = expf(v.y);
                v.z = expf(v.z); v.w = expf(v.w);
                rs += v.x + v.y + v.z + v.w;
            }
            if (DIVROW) { v.x *= inv; v.y *= inv; v.z *= inv; v.w *= inv; }
            *(float4*)&Cb[(long)m * ldc + n] = v;
        }
        if (ACT == 3) {
            rs += __shfl_xor_sync(0xffffffffu, rs, 1);
            if ((lane & 1) == 0) sm_l[wid >> 1][wm + mb * 16 + r] = rs;
        }
        __syncwarp();
    }

    if (ACT == 3) {
        __syncthreads();
        if (tid < 128) {
            float s = sm_l[0][tid] + sm_l[1][tid] + sm_l[2][tid] + sm_l[3][tid];
            lpart[(long)z * 8192 + blockIdx.x * 1024 + row0 + tid] = s;
        }
    }
}

// ---------------- Pack Wq|Wk -> [H][512][128] ----------------
__global__ __launch_bounds__(256)
void pack_wqk(const float* __restrict__ Wq, const float* __restrict__ Wk,
              float* __restrict__ Wqk)
{
    int idx = blockIdx.x * 256 + threadIdx.x;   // over H*512*64
    int h = idx >> 15, rem = idx & 32767;
    int d = rem >> 6, e = rem & 63;
    long base = (long)h * (Dd * 128) + (long)d * 128;
    Wqk[base + e]      = Wq[idx];
    Wqk[base + 64 + e] = Wk[idx];
}

// ---------------- Fused residual + LayerNorm, 512 cols ----------------
__global__ __launch_bounds__(256)
void residual_ln(const float* __restrict__ X, const float* __restrict__ Y,
                 const float* __restrict__ g, const float* __restrict__ be,
                 float* __restrict__ out)
{
    const int NC = Dd;
    long row = blockIdx.x;
    const float* x = X + row * NC;
    const float* y = Y + row * NC;
    float* o = out + row * NC;
    int tid = threadIdx.x;
    __shared__ float red[256];

    float v0 = x[tid] + y[tid];
    float v1 = x[tid + 256] + y[tid + 256];

    red[tid] = v0 + v1; __syncthreads();
    for (int s = 128; s > 0; s >>= 1) {
        if (tid < s) red[tid] += red[tid + s];
        __syncthreads();
    }
    float mu = red[0] * (1.f / NC); __syncthreads();

    float d0 = v0 - mu, d1 = v1 - mu;
    red[tid] = d0 * d0 + d1 * d1; __syncthreads();
    for (int s = 128; s > 0; s >>= 1) {
        if (tid < s) red[tid] += red[tid + s];
        __syncthreads();
    }
    float rstd = rsqrtf(red[0] * (1.f / NC) + 1e-5f);

    o[tid]       = d0 * rstd * g[tid]       + be[tid];
    o[tid + 256] = d1 * rstd * g[tid + 256] + be[tid + 256];
}

// ---------------- Launch ----------------
extern "C" void kernel_launch(void* const* d_in, const int* in_sizes, int n_in,
                              void* d_out, int out_size)
{
    const float* x  = (const float*)d_in[0];
    const float* Wq = (const float*)d_in[1];
    const float* Wk = (const float*)d_in[2];
    const float* Wv = (const float*)d_in[3];
    const float* Wo = (const float*)d_in[4];
    const float* W1 = (const float*)d_in[5];
    const float* b1 = (const float*)d_in[6];
    const float* W2 = (const float*)d_in[7];
    const float* b2 = (const float*)d_in[8];
    const float* g1 = (const float*)d_in[9];
    const float* be1= (const float*)d_in[10];
    const float* g2 = (const float*)d_in[11];
    const float* be2= (const float*)d_in[12];
    float* out = (float*)d_out;

    float *Wqk, *QK, *V, *Sc, *lp, *O, *attn, *x1, *h1, *f;
    cudaGetSymbolAddress((void**)&Wqk,  g_Wqk);
    cudaGetSymbolAddress((void**)&QK,   g_QK);
    cudaGetSymbolAddress((void**)&V,    g_V);
    cudaGetSymbolAddress((void**)&Sc,   g_S);
    cudaGetSymbolAddress((void**)&lp,   g_lpart);
    cudaGetSymbolAddress((void**)&O,    g_O);
    cudaGetSymbolAddress((void**)&attn, g_attn);
    cudaGetSymbolAddress((void**)&x1,   g_x1);
    cudaGetSymbolAddress((void**)&h1,   g_h1);
    cudaGetSymbolAddress((void**)&f,    g_f);

    // 0. pack Wq|Wk
    pack_wqk<<<(Hh*Dd*Ee)/256, 256>>>(Wq, Wk, Wqk);
    // 1. QK = x @ Wqk[h]   [4096,512]x[512,128] per head
    tgemm<false,0,false,false><<<dim3(1, 32, Hh), 256>>>(
        x, Wqk, QK, nullptr, nullptr, BS, 128, Dd, Dd, 128, 128, 1.f,
        0L, (long)Dd*128, (long)BS*128);
    // 2. V = x @ Wv[h]     [4096,512]x[512,512] per head
    tgemm<false,0,false,false><<<dim3(4, 32, Hh), 256>>>(
        x, Wv, V, nullptr, nullptr, BS, Dd, Dd, Dd, Dd, Dd, 1.f,
        0L, (long)Dd*Dd, (long)Bb*Ss*Dd);
    // 3. P = exp(Q @ K^T / 8), row partials -> lpart   per (h,b)
    tgemm<true,3,false,false><<<dim3(8, 8, Hh*Bb), 256>>>(
        QK, QK + 64, Sc, nullptr, lp, Ss, Ss, Ee, 128, 128, Ss, 0.125f,
        (long)Ss*128, (long)Ss*128, (long)Ss*Ss);
    // 4. O = (P @ V) / rowsum   per (h,b): [1024,1024]x[1024,512]
    tgemm<false,0,false,true><<<dim3(4, 8, Hh*Bb), 256>>>(
        Sc, V, O, nullptr, lp, Ss, Dd, Ss, Ss, Dd, Dd, 1.f,
        (long)Ss*Ss, (long)Ss*Dd, (long)Ss*Dd);
    // 5. attn = a @ Wo with k=(h,d) permutation folded into the loads
    tgemm<false,0,true,false><<<dim3(4, 32, 1), 256>>>(
        O, Wo, attn, nullptr, nullptr, BS, Dd, DH, Dd, Dd, Dd, 1.f, 0L, 0L, 0L);
    // 6. x1 = LN(x + attn)
    residual_ln<<<BS, 256>>>(x, attn, g1, be1, x1);
    // 7. h1 = ELU(x1 @ W1 + b1)
    tgemm<false,2,false,false><<<dim3(4, 32, 1), 256>>>(
        x1, W1, h1, b1, nullptr, BS, Dd, Dd, Dd, Dd, Dd, 1.f, 0L, 0L, 0L);
    // 8. f = h1 @ W2 + b2
    tgemm<false,1,false,false><<<dim3(4, 32, 1), 256>>>(
        h1, W2, f, b2, nullptr, BS, Dd, Dd, Dd, Dd, Dd, 1.f, 0L, 0L, 0L);
    // 9. out = LN(x1 + f)
    residual_ln<<<BS, 256>>>(x1, f, g2, be2, out);
}

// round 8
// speedup vs baseline: 4.9225x; 2.0924x over previous
#include <cuda_runtime.h>
#include <cuda_fp16.h>
#include <mma.h>
#include <math.h>
#include <stdint.h>

using namespace nvcuda;

// Problem constants
#define Bb 4
#define Ss 1024
#define Dd 512
#define Ee 64
#define Hh 8
#define BS (Bb*Ss)      // 4096
#define DH (Dd*Hh)      // 4096

// ---------------- Scratch (device globals; no allocation allowed) ----------------
__device__ float g_Wqk[Hh*Dd*128];      // packed [H][512][128] = Wq | Wk
__device__ float g_QK[Hh*BS*128];       // [H,B,S,128]: Q|K per row
__device__ float g_V[Hh*Bb*Ss*Dd];      // [H,B,S,D]
__device__ float g_S[(long)Hh*Bb*Ss*Ss];// [H,B,S,S] unnormalized probs P=exp(s)
__device__ float g_lpart[Hh*Bb*8*Ss];   // [z][xtile(8)][row] partial row sums
__device__ float g_O[Hh*BS*Dd];         // [H,B,S,D] attention output (pre-Wo)
__device__ float g_attn[BS*Dd];
__device__ float g_x1[BS*Dd];
__device__ float g_h1[BS*Dd];
__device__ float g_f[BS*Dd];

// ---------------- FP16 WMMA GEMM ----------------
// C = alpha * A @ op(B) [+bias / +ELU / exp+rowsum], batched over blockIdx.z.
// Inputs fp32 in gmem, converted to fp16 at SMEM store; accumulate fp32.
// TRANSB: B is [N,K] row-major.
// KPERM (Wo GEMM): k = h*512 + d;
//   A element (m,k) = O[h, m, d]      -> A + h*BS*Dd + m*512 + d
//   B element (k,n) = Wo[d*8 + h, n]  -> B + (d*8+h)*512 + n
// ACT: 0 none, 1 +bias, 2 +bias+ELU, 3 exp(alpha*v) + row partial sums -> lpart
// DIVROW: divide each output row by sum of 8 lpart partials.
// Block 128x128, BK=32, 2-stage register prefetch; 8 warps of 64x32 (4x2 m16n16k16).
//
// STATIC SMEM (halves), per stage 10240:
//   As: [128][40] row-major (m x k), ld=40
//   Bs: TRANSB -> [128][40] (element (k,n) at n*40+k, col-major frags, ld=40)
//       else   -> [32][136] row-major (k x n), ld=136 (4352 <= 5120 slot)
// Epilogue reuses pool as float scratch: 8 warps x [16][40] = 20480B <= 40960B.
#define STAGE_H 10240

template<bool TRANSB, int ACT, bool KPERM, bool DIVROW>
__global__ __launch_bounds__(256, 2)
void tgemm(const float* __restrict__ A, const float* __restrict__ B,
           float* __restrict__ C, const float* __restrict__ bias,
           float* __restrict__ lpart,
           int M, int N, int K, int lda, int ldb, int ldc,
           float alpha, long sA, long sB, long sC)
{
    const int BK = 32;
    __shared__ __align__(32) __half pool[2 * STAGE_H];
    __shared__ float sm_l[4][128];

    const int z = blockIdx.z;
    const float* Ab = A + (long)z * sA;
    const float* Bp = B + (long)z * sB;
    float* Cb = C + (long)z * sC;

    const int tid = threadIdx.x;
    const int wid = tid >> 5, lane = tid & 31;
    const int wm = (wid & 1) * 64, wn = (wid >> 1) * 32;
    const int row0 = blockIdx.y * 128, col0 = blockIdx.x * 128;

    wmma::fragment<wmma::accumulator, 16, 16, 16, float> acc[4][2];
    #pragma unroll
    for (int i = 0; i < 4; i++)
        #pragma unroll
        for (int j = 0; j < 2; j++)
            wmma::fill_fragment(acc[i][j], 0.0f);

    float4 ra[4], rb[4];

    auto ldg = [&](int k0) {
        #pragma unroll
        for (int i = 0; i < 4; i++) {
            int e = tid + i * 256;
            int m = row0 + (e >> 3);
            int k = k0 + 4 * (e & 7);
            const float* s;
            if (KPERM) s = A + (long)(k >> 9) * ((long)BS * Dd) + (long)m * 512 + (k & 511);
            else       s = Ab + (long)m * lda + k;
            ra[i] = *(const float4*)s;
        }
        if (TRANSB) {
            #pragma unroll
            for (int i = 0; i < 4; i++) {
                int e = tid + i * 256;
                int n = col0 + (e >> 3);
                int k = k0 + 4 * (e & 7);
                rb[i] = *(const float4*)(Bp + (long)n * ldb + k);
            }
        } else {
            #pragma unroll
            for (int i = 0; i < 4; i++) {
                int e = tid + i * 256;
                int k = k0 + (e >> 5);
                int n = col0 + 4 * (e & 31);
                const float* s;
                if (KPERM) s = B + ((long)(k & 511) * 8 + (k >> 9)) * 512 + n;
                else       s = Bp + (long)k * ldb + n;
                rb[i] = *(const float4*)s;
            }
        }
    };

    auto sts = [&](int st) {
        __half* As_ = pool + st * STAGE_H;
        __half* Bs_ = pool + st * STAGE_H + 5120;
        #pragma unroll
        for (int i = 0; i < 4; i++) {
            int e = tid + i * 256;
            int m = e >> 3, kq = 4 * (e & 7);
            __half2* d = (__half2*)(As_ + m * 40 + kq);
            d[0] = __floats2half2_rn(ra[i].x, ra[i].y);
            d[1] = __floats2half2_rn(ra[i].z, ra[i].w);
        }
        if (TRANSB) {
            #pragma unroll
            for (int i = 0; i < 4; i++) {
                int e = tid + i * 256;
                int n = e >> 3, kq = 4 * (e & 7);
                __half2* d = (__half2*)(Bs_ + n * 40 + kq);
                d[0] = __floats2half2_rn(rb[i].x, rb[i].y);
                d[1] = __floats2half2_rn(rb[i].z, rb[i].w);
            }
        } else {
            #pragma unroll
            for (int i = 0; i < 4; i++) {
                int e = tid + i * 256;
                int kk = e >> 5, n4 = 4 * (e & 31);
                __half2* d = (__half2*)(Bs_ + kk * 136 + n4);
                d[0] = __floats2half2_rn(rb[i].x, rb[i].y);
                d[1] = __floats2half2_rn(rb[i].z, rb[i].w);
            }
        }
    };

    auto comp = [&](int st) {
        const __half* As_ = pool + st * STAGE_H;
        const __half* Bs_ = pool + st * STAGE_H + 5120;
        #pragma unroll
        for (int kb = 0; kb < BK; kb += 16) {
            wmma::fragment<wmma::matrix_a, 16, 16, 16, __half, wmma::row_major> af[4];
            #pragma unroll
            for (int mb = 0; mb < 4; mb++)
                wmma::load_matrix_sync(af[mb], As_ + (wm + mb * 16) * 40 + kb, 40);
            #pragma unroll
            for (int nb = 0; nb < 2; nb++) {
                if (TRANSB) {
                    wmma::fragment<wmma::matrix_b, 16, 16, 16, __half, wmma::col_major> bf;
                    wmma::load_matrix_sync(bf, Bs_ + (wn + nb * 16) * 40 + kb, 40);
                    #pragma unroll
                    for (int mb = 0; mb < 4; mb++)
                        wmma::mma_sync(acc[mb][nb], af[mb], bf, acc[mb][nb]);
                } else {
                    wmma::fragment<wmma::matrix_b, 16, 16, 16, __half, wmma::row_major> bf;
                    wmma::load_matrix_sync(bf, Bs_ + kb * 136 + wn + nb * 16, 136);
                    #pragma unroll
                    for (int mb = 0; mb < 4; mb++)
                        wmma::mma_sync(acc[mb][nb], af[mb], bf, acc[mb][nb]);
                }
            }
        }
    };

    ldg(0); sts(0); __syncthreads();
    const int nk = K / BK;
    int st = 0;
    for (int kt = 1; kt < nk; kt++) {
        ldg(kt * BK);
        comp(st);
        sts(st ^ 1);
        __syncthreads();
        st ^= 1;
    }
    comp(st);
    __syncthreads();   // done reading smem; reuse as epilogue scratch

    // Epilogue: stage 16x32 warp slabs through smem for explicit (row,col) math.
    float* scratch = (float*)pool + wid * 640;   // [16][40]
    const int r = lane >> 1, chalf = (lane & 1) * 16;

    #pragma unroll
    for (int mb = 0; mb < 4; mb++) {
        wmma::store_matrix_sync(scratch,      acc[mb][0], 40, wmma::mem_row_major);
        wmma::store_matrix_sync(scratch + 16, acc[mb][1], 40, wmma::mem_row_major);
        __syncwarp();

        const int m = row0 + wm + mb * 16 + r;
        float inv = 1.0f;
        if (DIVROW) {
            float ls = 0.f;
            #pragma unroll
            for (int j = 0; j < 8; j++) ls += lpart[(long)z * 8192 + j * 1024 + m];
            inv = 1.0f / ls;
        }
        float rs = 0.f;
        #pragma unroll
        for (int it = 0; it < 4; it++) {
            int c = chalf + it * 4;
            float4 v = *(float4*)(scratch + r * 40 + c);
            int n = col0 + wn + c;
            v.x *= alpha; v.y *= alpha; v.z *= alpha; v.w *= alpha;
            if (ACT == 1 || ACT == 2) {
                v.x += bias[n];     v.y += bias[n + 1];
                v.z += bias[n + 2]; v.w += bias[n + 3];
            }
            if (ACT == 2) {
                v.x = v.x > 0.f ? v.x : expm1f(v.x);
                v.y = v.y > 0.f ? v.y : expm1f(v.y);
                v.z = v.z > 0.f ? v.z : expm1f(v.z);
                v.w = v.w > 0.f ? v.w : expm1f(v.w);
            }
            if (ACT == 3) {
                v.x = __expf(v.x); v.y = __expf(v.y);
                v.z = __expf(v.z); v.w = __expf(v.w);
                rs += v.x + v.y + v.z + v.w;
            }
            if (DIVROW) { v.x *= inv; v.y *= inv; v.z *= inv; v.w *= inv; }
            *(float4*)&Cb[(long)m * ldc + n] = v;
        }
        if (ACT == 3) {
            rs += __shfl_xor_sync(0xffffffffu, rs, 1);
            if ((lane & 1) == 0) sm_l[wid >> 1][wm + mb * 16 + r] = rs;
        }
        __syncwarp();
    }

    if (ACT == 3) {
        __syncthreads();
        if (tid < 128) {
            float s = sm_l[0][tid] + sm_l[1][tid] + sm_l[2][tid] + sm_l[3][tid];
            lpart[(long)z * 8192 + blockIdx.x * 1024 + row0 + tid] = s;
        }
    }
}

// ---------------- Pack Wq|Wk -> [H][512][128] ----------------
__global__ __launch_bounds__(256)
void pack_wqk(const float* __restrict__ Wq, const float* __restrict__ Wk,
              float* __restrict__ Wqk)
{
    int idx = blockIdx.x * 256 + threadIdx.x;   // over H*512*64
    int h = idx >> 15, rem = idx & 32767;
    int d = rem >> 6, e = rem & 63;
    long base = (long)h * (Dd * 128) + (long)d * 128;
    Wqk[base + e]      = Wq[idx];
    Wqk[base + 64 + e] = Wk[idx];
}

// ---------------- Fused residual + LayerNorm, 512 cols ----------------
__global__ __launch_bounds__(256)
void residual_ln(const float* __restrict__ X, const float* __restrict__ Y,
                 const float* __restrict__ g, const float* __restrict__ be,
                 float* __restrict__ out)
{
    const int NC = Dd;
    long row = blockIdx.x;
    const float* x = X + row * NC;
    const float* y = Y + row * NC;
    float* o = out + row * NC;
    int tid = threadIdx.x;
    __shared__ float red[256];

    float v0 = x[tid] + y[tid];
    float v1 = x[tid + 256] + y[tid + 256];

    red[tid] = v0 + v1; __syncthreads();
    for (int s = 128; s > 0; s >>= 1) {
        if (tid < s) red[tid] += red[tid + s];
        __syncthreads();
    }
    float mu = red[0] * (1.f / NC); __syncthreads();

    float d0 = v0 - mu, d1 = v1 - mu;
    red[tid] = d0 * d0 + d1 * d1; __syncthreads();
    for (int s = 128; s > 0; s >>= 1) {
        if (tid < s) red[tid] += red[tid + s];
        __syncthreads();
    }
    float rstd = rsqrtf(red[0] * (1.f / NC) + 1e-5f);

    o[tid]       = d0 * rstd * g[tid]       + be[tid];
    o[tid + 256] = d1 * rstd * g[tid + 256] + be[tid + 256];
}

// ---------------- Launch ----------------
extern "C" void kernel_launch(void* const* d_in, const int* in_sizes, int n_in,
                              void* d_out, int out_size)
{
    const float* x  = (const float*)d_in[0];
    const float* Wq = (const float*)d_in[1];
    const float* Wk = (const float*)d_in[2];
    const float* Wv = (const float*)d_in[3];
    const float* Wo = (const float*)d_in[4];
    const float* W1 = (const float*)d_in[5];
    const float* b1 = (const float*)d_in[6];
    const float* W2 = (const float*)d_in[7];
    const float* b2 = (const float*)d_in[8];
    const float* g1 = (const float*)d_in[9];
    const float* be1= (const float*)d_in[10];
    const float* g2 = (const float*)d_in[11];
    const float* be2= (const float*)d_in[12];
    float* out = (float*)d_out;

    float *Wqk, *QK, *V, *Sc, *lp, *O, *attn, *x1, *h1, *f;
    cudaGetSymbolAddress((void**)&Wqk,  g_Wqk);
    cudaGetSymbolAddress((void**)&QK,   g_QK);
    cudaGetSymbolAddress((void**)&V,    g_V);
    cudaGetSymbolAddress((void**)&Sc,   g_S);
    cudaGetSymbolAddress((void**)&lp,   g_lpart);
    cudaGetSymbolAddress((void**)&O,    g_O);
    cudaGetSymbolAddress((void**)&attn, g_attn);
    cudaGetSymbolAddress((void**)&x1,   g_x1);
    cudaGetSymbolAddress((void**)&h1,   g_h1);
    cudaGetSymbolAddress((void**)&f,    g_f);

    // 0. pack Wq|Wk
    pack_wqk<<<(Hh*Dd*Ee)/256, 256>>>(Wq, Wk, Wqk);
    // 1. QK = x @ Wqk[h]   [4096,512]x[512,128] per head
    tgemm<false,0,false,false><<<dim3(1, 32, Hh), 256>>>(
        x, Wqk, QK, nullptr, nullptr, BS, 128, Dd, Dd, 128, 128, 1.f,
        0L, (long)Dd*128, (long)BS*128);
    // 2. V = x @ Wv[h]     [4096,512]x[512,512] per head
    tgemm<false,0,false,false><<<dim3(4, 32, Hh), 256>>>(
        x, Wv, V, nullptr, nullptr, BS, Dd, Dd, Dd, Dd, Dd, 1.f,
        0L, (long)Dd*Dd, (long)Bb*Ss*Dd);
    // 3. P = exp(Q @ K^T / 8), row partials -> lpart   per (h,b)
    tgemm<true,3,false,false><<<dim3(8, 8, Hh*Bb), 256>>>(
        QK, QK + 64, Sc, nullptr, lp, Ss, Ss, Ee, 128, 128, Ss, 0.125f,
        (long)Ss*128, (long)Ss*128, (long)Ss*Ss);
    // 4. O = (P @ V) / rowsum   per (h,b): [1024,1024]x[1024,512]
    tgemm<false,0,false,true><<<dim3(4, 8, Hh*Bb), 256>>>(
        Sc, V, O, nullptr, lp, Ss, Dd, Ss, Ss, Dd, Dd, 1.f,
        (long)Ss*Ss, (long)Ss*Dd, (long)Ss*Dd);
    // 5. attn = a @ Wo with k=(h,d) permutation folded into the loads
    tgemm<false,0,true,false><<<dim3(4, 32, 1), 256>>>(
        O, Wo, attn, nullptr, nullptr, BS, Dd, DH, Dd, Dd, Dd, 1.f, 0L, 0L, 0L);
    // 6. x1 = LN(x + attn)
    residual_ln<<<BS, 256>>>(x, attn, g1, be1, x1);
    // 7. h1 = ELU(x1 @ W1 + b1)
    tgemm<false,2,false,false><<<dim3(4, 32, 1), 256>>>(
        x1, W1, h1, b1, nullptr, BS, Dd, Dd, Dd, Dd, Dd, 1.f, 0L, 0L, 0L);
    // 8. f = h1 @ W2 + b2
    tgemm<false,1,false,false><<<dim3(4, 32, 1), 256>>>(
        h1, W2, f, b2, nullptr, BS, Dd, Dd, Dd, Dd, Dd, 1.f, 0L, 0L, 0L);
    // 9. out = LN(x1 + f)
    residual_ln<<<BS, 256>>>(x1, f, g2, be2, out);
}

// round 13
// speedup vs baseline: 7.6700x; 1.5581x over previous
#include <cuda_runtime.h>
#include <cuda_fp16.h>
#include <mma.h>
#include <math.h>
#include <stdint.h>

using namespace nvcuda;

// Problem constants
#define Bb 4
#define Ss 1024
#define Dd 512
#define Ee 64
#define Hh 8
#define BS (Bb*Ss)      // 4096
#define DH (Dd*Hh)      // 4096

// ---------------- Scratch (device globals; no allocation allowed) ----------------
__device__ __half g_xh[BS*Dd];            // fp16 copy of x
__device__ __half g_Wqkh[Hh*Dd*128];      // packed fp16 [H][512][128] = Wq | Wk
__device__ __half g_Wvh[Hh*Dd*Dd];
__device__ __half g_Woh[DH*Dd];           // fp16 Wo (original layout)
__device__ __half g_W1h[Dd*Dd];
__device__ __half g_W2h[Dd*Dd];
__device__ __half g_QK[Hh*BS*128];        // [H,B,S,128]: Q|K per row (fp16)
__device__ __half g_V[Hh*Bb*Ss*Dd];       // [H,B,S,D] fp16
__device__ __half g_P[(long)Hh*Bb*Ss*Ss]; // [z][1024][1024] unnormalized probs (64MB fp16)
__device__ float  g_lpart[Hh*Bb*8*Ss];    // [z][xtile(8)][row] partial row sums
__device__ __half g_O[Hh*BS*Dd];          // [H,B,S,D] attention out (fp16, pre-Wo)
__device__ float  g_attn[BS*Dd];
__device__ float  g_x1[BS*Dd];
__device__ __half g_x1h[BS*Dd];
__device__ __half g_h1[BS*Dd];
__device__ float  g_f[BS*Dd];

// ---------------- helpers ----------------
__device__ __forceinline__ uint32_t s2u(const void* p) {
    uint32_t a;
    asm("{ .reg .u64 t; cvta.to.shared.u64 t, %1; cvt.u32.u64 %0, t; }" : "=r"(a) : "l"(p));
    return a;
}
__device__ __forceinline__ void cp16(uint32_t dst, const void* src) {
    asm volatile("cp.async.cg.shared.global [%0], [%1], 16;" :: "r"(dst), "l"(src) : "memory");
}
union H2U2 { __half2 h[2]; uint2 u; };

// ---------------- FP16 WMMA GEMM, fp16 gmem operands, cp.async pipeline ----------------
// C = alpha * A @ op(B) [+bias / +ELU / exp+rowsum], batched over blockIdx.z.
// TRANSB: B is [N,K] row-major (fp16). Else B is [K,N] row-major.
// KPERM (Wo GEMM): k = h*512 + d;
//   A element (m,k) = O[h, m, d] ; B element (k,n) = Wo[d*8 + h, n]
// ACT: 0 none, 1 +bias, 2 +bias+ELU, 3 exp(alpha*v) + row partial sums -> lpart
// DIVROW: divide rows by sum of 8 lpart partials.  OUTH: C is fp16.
// Block 128x128, BK=32, 2-stage cp.async; 8 warps of 64x32 (4x2 m16n16k16).
// STATIC SMEM (halves), per stage 10240 (20480 B):
//   As: [128][40] ld=40 (5120 halves, byte off 0)
//   Bs: byte off 10240; TRANSB -> [128][40] ld=40 ; else [32][136] ld=136
#define STAGE_H 10240
#define STAGE_B (STAGE_H*2)
#define B_OFF_B (5120*2)

template<bool TRANSB, int ACT, bool KPERM, bool DIVROW, bool OUTH>
__global__ __launch_bounds__(256, 2)
void tgemm(const __half* __restrict__ A, const __half* __restrict__ B,
           void* __restrict__ Cv, const float* __restrict__ bias,
           float* __restrict__ lpart,
           int M, int N, int K, int lda, int ldb, int ldc,
           float alpha, long sA, long sB, long sC)
{
    const int BK = 32;
    __shared__ __align__(128) __half pool[2 * STAGE_H];
    __shared__ float sm_l[4][128];

    const int z = blockIdx.z;
    const __half* Ab = A + (long)z * sA;
    const __half* Bp = B + (long)z * sB;

    const int tid = threadIdx.x;
    const int wid = tid >> 5, lane = tid & 31;
    const int wm = (wid & 1) * 64, wn = (wid >> 1) * 32;
    const int row0 = blockIdx.y * 128, col0 = blockIdx.x * 128;
    const uint32_t base = s2u(pool);

    wmma::fragment<wmma::accumulator, 16, 16, 16, float> acc[4][2];
    #pragma unroll
    for (int i = 0; i < 4; i++)
        #pragma unroll
        for (int j = 0; j < 2; j++)
            wmma::fill_fragment(acc[i][j], 0.0f);

    auto load_stage = [&](int kt) {
        const int k0 = kt * BK;
        const uint32_t sb = base + (uint32_t)(kt & 1) * STAGE_B;
        // A: 128 rows x 32 halves, chunks of 8 halves
        #pragma unroll
        for (int i = 0; i < 2; i++) {
            int e = tid + i * 256;
            int r = e >> 2, c = e & 3;
            int k = k0 + 8 * c;
            const __half* src;
            if (KPERM) src = A + (long)(k >> 9) * ((long)BS * 512) + (long)(row0 + r) * 512 + (k & 511);
            else       src = Ab + (long)(row0 + r) * lda + k;
            cp16(sb + (uint32_t)(r * 40 + 8 * c) * 2, src);
        }
        if (TRANSB) {
            #pragma unroll
            for (int i = 0; i < 2; i++) {
                int e = tid + i * 256;
                int r = e >> 2, c = e & 3;
                const __half* src = Bp + (long)(col0 + r) * ldb + k0 + 8 * c;
                cp16(sb + (uint32_t)B_OFF_B + (uint32_t)(r * 40 + 8 * c) * 2, src);
            }
        } else {
            #pragma unroll
            for (int i = 0; i < 2; i++) {
                int e = tid + i * 256;
                int kk = e >> 4, c = e & 15;
                int k = k0 + kk, n = col0 + 8 * c;
                const __half* src;
                if (KPERM) src = B + ((long)(k & 511) * 8 + (k >> 9)) * 512 + n;
                else       src = Bp + (long)k * ldb + n;
                cp16(sb + (uint32_t)B_OFF_B + (uint32_t)(kk * 136 + 8 * c) * 2, src);
            }
        }
        asm volatile("cp.async.commit_group;" ::: "memory");
    };

    auto comp = [&](int st) {
        const __half* As_ = pool + st * STAGE_H;
        const __half* Bs_ = pool + st * STAGE_H + 5120;
        #pragma unroll
        for (int kb = 0; kb < BK; kb += 16) {
            wmma::fragment<wmma::matrix_a, 16, 16, 16, __half, wmma::row_major> af[4];
            #pragma unroll
            for (int mb = 0; mb < 4; mb++)
                wmma::load_matrix_sync(af[mb], As_ + (wm + mb * 16) * 40 + kb, 40);
            #pragma unroll
            for (int nb = 0; nb < 2; nb++) {
                if (TRANSB) {
                    wmma::fragment<wmma::matrix_b, 16, 16, 16, __half, wmma::col_major> bf;
                    wmma::load_matrix_sync(bf, Bs_ + (wn + nb * 16) * 40 + kb, 40);
                    #pragma unroll
                    for (int mb = 0; mb < 4; mb++)
                        wmma::mma_sync(acc[mb][nb], af[mb], bf, acc[mb][nb]);
                } else {
                    wmma::fragment<wmma::matrix_b, 16, 16, 16, __half, wmma::row_major> bf;
                    wmma::load_matrix_sync(bf, Bs_ + kb * 136 + wn + nb * 16, 136);
                    #pragma unroll
                    for (int mb = 0; mb < 4; mb++)
                        wmma::mma_sync(acc[mb][nb], af[mb], bf, acc[mb][nb]);
                }
            }
        }
    };

    const int nk = K / BK;
    load_stage(0);
    for (int kt = 0; kt < nk; kt++) {
        if (kt + 1 < nk) {
            load_stage(kt + 1);
            asm volatile("cp.async.wait_group 1;" ::: "memory");
        } else {
            asm volatile("cp.async.wait_group 0;" ::: "memory");
        }
        __syncthreads();
        comp(kt & 1);
        __syncthreads();
    }

    // Epilogue: stage 16x32 warp slabs through smem for explicit (row,col) math.
    float* scratch = (float*)pool + wid * 640;   // [16][40]
    const int r = lane >> 1, chalf = (lane & 1) * 16;

    #pragma unroll
    for (int mb = 0; mb < 4; mb++) {
        wmma::store_matrix_sync(scratch,      acc[mb][0], 40, wmma::mem_row_major);
        wmma::store_matrix_sync(scratch + 16, acc[mb][1], 40, wmma::mem_row_major);
        __syncwarp();

        const int m = row0 + wm + mb * 16 + r;
        float inv = 1.0f;
        if (DIVROW) {
            float ls = 0.f;
            #pragma unroll
            for (int j = 0; j < 8; j++) ls += lpart[(long)z * 8192 + j * 1024 + m];
            inv = 1.0f / ls;
        }
        float rs = 0.f;
        #pragma unroll
        for (int it = 0; it < 4; it++) {
            int c = chalf + it * 4;
            float4 v = *(float4*)(scratch + r * 40 + c);
            int n = col0 + wn + c;
            v.x *= alpha; v.y *= alpha; v.z *= alpha; v.w *= alpha;
            if (ACT == 1 || ACT == 2) {
                v.x += bias[n];     v.y += bias[n + 1];
                v.z += bias[n + 2]; v.w += bias[n + 3];
            }
            if (ACT == 2) {
                v.x = v.x > 0.f ? v.x : expm1f(v.x);
                v.y = v.y > 0.f ? v.y : expm1f(v.y);
                v.z = v.z > 0.f ? v.z : expm1f(v.z);
                v.w = v.w > 0.f ? v.w : expm1f(v.w);
            }
            if (ACT == 3) {
                v.x = __expf(v.x); v.y = __expf(v.y);
                v.z = __expf(v.z); v.w = __expf(v.w);
                rs += v.x + v.y + v.z + v.w;
            }
            if (DIVROW) { v.x *= inv; v.y *= inv; v.z *= inv; v.w *= inv; }
            if (OUTH) {
                __half* Ch = (__half*)Cv + (long)z * sC;
                H2U2 pk;
                pk.h[0] = __floats2half2_rn(v.x, v.y);
                pk.h[1] = __floats2half2_rn(v.z, v.w);
                *(uint2*)&Ch[(long)m * ldc + n] = pk.u;
            } else {
                float* Cf = (float*)Cv + (long)z * sC;
                *(float4*)&Cf[(long)m * ldc + n] = v;
            }
        }
        if (ACT == 3) {
            rs += __shfl_xor_sync(0xffffffffu, rs, 1);
            if ((lane & 1) == 0) sm_l[wid >> 1][wm + mb * 16 + r] = rs;
        }
        __syncwarp();
    }

    if (ACT == 3) {
        __syncthreads();
        if (tid < 128) {
            float s = sm_l[0][tid] + sm_l[1][tid] + sm_l[2][tid] + sm_l[3][tid];
            lpart[(long)z * 8192 + blockIdx.x * 1024 + row0 + tid] = s;
        }
    }
}

// ---------------- fp32 -> fp16 elementwise ----------------
__global__ __launch_bounds__(256)
void cvt_f2h(const float* __restrict__ in, __half* __restrict__ out, int n4)
{
    int i = blockIdx.x * 256 + threadIdx.x;
    if (i < n4) {
        float4 v = ((const float4*)in)[i];
        H2U2 pk;
        pk.h[0] = __floats2half2_rn(v.x, v.y);
        pk.h[1] = __floats2half2_rn(v.z, v.w);
        ((uint2*)out)[i] = pk.u;
    }
}

// ---------------- Pack Wq|Wk -> fp16 [H][512][128] ----------------
__global__ __launch_bounds__(256)
void pack_wqk(const float* __restrict__ Wq, const float* __restrict__ Wk,
              __half* __restrict__ Wqk)
{
    int idx = blockIdx.x * 256 + threadIdx.x;   // over H*512*64
    int h = idx >> 15, rem = idx & 32767;
    int d = rem >> 6, e = rem & 63;
    long base = (long)h * (Dd * 128) + (long)d * 128;
    Wqk[base + e]      = __float2half(Wq[idx]);
    Wqk[base + 64 + e] = __float2half(Wk[idx]);
}

// ---------------- Fused residual + LayerNorm, 512 cols (+optional fp16 copy) ----------------
__global__ __launch_bounds__(256)
void residual_ln(const float* __restrict__ X, const float* __restrict__ Y,
                 const float* __restrict__ g, const float* __restrict__ be,
                 float* __restrict__ out, __half* __restrict__ outh)
{
    const int NC = Dd;
    long row = blockIdx.x;
    const float* x = X + row * NC;
    const float* y = Y + row * NC;
    float* o = out + row * NC;
    int tid = threadIdx.x;
    __shared__ float red[256];

    float v0 = x[tid] + y[tid];
    float v1 = x[tid + 256] + y[tid + 256];

    red[tid] = v0 + v1; __syncthreads();
    for (int s = 128; s > 0; s >>= 1) {
        if (tid < s) red[tid] += red[tid + s];
        __syncthreads();
    }
    float mu = red[0] * (1.f / NC); __syncthreads();

    float d0 = v0 - mu, d1 = v1 - mu;
    red[tid] = d0 * d0 + d1 * d1; __syncthreads();
    for (int s = 128; s > 0; s >>= 1) {
        if (tid < s) red[tid] += red[tid + s];
        __syncthreads();
    }
    float rstd = rsqrtf(red[0] * (1.f / NC) + 1e-5f);

    float r0 = d0 * rstd * g[tid]       + be[tid];
    float r1 = d1 * rstd * g[tid + 256] + be[tid + 256];
    o[tid] = r0;
    o[tid + 256] = r1;
    if (outh) {
        outh[row * NC + tid]       = __float2half(r0);
        outh[row * NC + tid + 256] = __float2half(r1);
    }
}

// ---------------- Launch ----------------
extern "C" void kernel_launch(void* const* d_in, const int* in_sizes, int n_in,
                              void* d_out, int out_size)
{
    const float* x  = (const float*)d_in[0];
    const float* Wq = (const float*)d_in[1];
    const float* Wk = (const float*)d_in[2];
    const float* Wv = (const float*)d_in[3];
    const float* Wo = (const float*)d_in[4];
    const float* W1 = (const float*)d_in[5];
    const float* b1 = (const float*)d_in[6];
    const float* W2 = (const float*)d_in[7];
    const float* b2 = (const float*)d_in[8];
    const float* g1 = (const float*)d_in[9];
    const float* be1= (const float*)d_in[10];
    const float* g2 = (const float*)d_in[11];
    const float* be2= (const float*)d_in[12];
    float* out = (float*)d_out;

    __half *xh, *Wqkh, *Wvh, *Woh, *W1h, *W2h, *QK, *V, *P, *O, *x1h, *h1;
    float *lp, *attn, *x1, *f;
    cudaGetSymbolAddress((void**)&xh,   g_xh);
    cudaGetSymbolAddress((void**)&Wqkh, g_Wqkh);
    cudaGetSymbolAddress((void**)&Wvh,  g_Wvh);
    cudaGetSymbolAddress((void**)&Woh,  g_Woh);
    cudaGetSymbolAddress((void**)&W1h,  g_W1h);
    cudaGetSymbolAddress((void**)&W2h,  g_W2h);
    cudaGetSymbolAddress((void**)&QK,   g_QK);
    cudaGetSymbolAddress((void**)&V,    g_V);
    cudaGetSymbolAddress((void**)&P,    g_P);
    cudaGetSymbolAddress((void**)&lp,   g_lpart);
    cudaGetSymbolAddress((void**)&O,    g_O);
    cudaGetSymbolAddress((void**)&attn, g_attn);
    cudaGetSymbolAddress((void**)&x1,   g_x1);
    cudaGetSymbolAddress((void**)&x1h,  g_x1h);
    cudaGetSymbolAddress((void**)&h1,   g_h1);
    cudaGetSymbolAddress((void**)&f,    g_f);

    // 0. conversions / packs
    cvt_f2h<<<(BS*Dd/4 + 255)/256, 256>>>(x,  xh,  BS*Dd/4);
    pack_wqk<<<(Hh*Dd*Ee)/256, 256>>>(Wq, Wk, Wqkh);
    cvt_f2h<<<(Hh*Dd*Dd/4 + 255)/256, 256>>>(Wv, Wvh, Hh*Dd*Dd/4);
    cvt_f2h<<<(DH*Dd/4 + 255)/256, 256>>>(Wo, Woh, DH*Dd/4);
    cvt_f2h<<<(Dd*Dd/4 + 255)/256, 256>>>(W1, W1h, Dd*Dd/4);
    cvt_f2h<<<(Dd*Dd/4 + 255)/256, 256>>>(W2, W2h, Dd*Dd/4);

    // 1. QK = x @ Wqk[h]   [4096,512]x[512,128] per head, fp16 out
    tgemm<false,0,false,false,true><<<dim3(1, 32, Hh), 256>>>(
        xh, Wqkh, QK, nullptr, nullptr, BS, 128, Dd, Dd, 128, 128, 1.f,
        0L, (long)Dd*128, (long)BS*128);
    // 2. V = x @ Wv[h]     [4096,512]x[512,512] per head, fp16 out
    tgemm<false,0,false,false,true><<<dim3(4, 32, Hh), 256>>>(
        xh, Wvh, V, nullptr, nullptr, BS, Dd, Dd, Dd, Dd, Dd, 1.f,
        0L, (long)Dd*Dd, (long)Bb*Ss*Dd);
    // 3. P = exp(Q @ K^T / 8), row partials -> lpart   per (h,b), fp16 out
    tgemm<true,3,false,false,true><<<dim3(8, 8, Hh*Bb), 256>>>(
        QK, QK + 64, P, nullptr, lp, Ss, Ss, Ee, 128, 128, Ss, 0.125f,
        (long)Ss*128, (long)Ss*128, (long)Ss*Ss);
    // 4. O = (P @ V) / rowsum   per (h,b): [1024,1024]x[1024,512], fp16 out
    tgemm<false,0,false,true,true><<<dim3(4, 8, Hh*Bb), 256>>>(
        P, V, O, nullptr, lp, Ss, Dd, Ss, Ss, Dd, Dd, 1.f,
        (long)Ss*Ss, (long)Ss*Dd, (long)Ss*Dd);
    // 5. attn = a @ Wo with k=(h,d) permutation folded into the loads, fp32 out
    tgemm<false,0,true,false,false><<<dim3(4, 32, 1), 256>>>(
        O, Woh, attn, nullptr, nullptr, BS, Dd, DH, Dd, Dd, Dd, 1.f, 0L, 0L, 0L);
    // 6. x1 = LN(x + attn)  (fp32 + fp16 copy)
    residual_ln<<<BS, 256>>>(x, attn, g1, be1, x1, x1h);
    // 7. h1 = ELU(x1 @ W1 + b1), fp16 out
    tgemm<false,2,false,false,true><<<dim3(4, 32, 1), 256>>>(
        x1h, W1h, h1, b1, nullptr, BS, Dd, Dd, Dd, Dd, Dd, 1.f, 0L, 0L, 0L);
    // 8. f = h1 @ W2 + b2, fp32 out
    tgemm<false,1,false,false,false><<<dim3(4, 32, 1), 256>>>(
        h1, W2h, f, b2, nullptr, BS, Dd, Dd, Dd, Dd, Dd, 1.f, 0L, 0L, 0L);
    // 9. out = LN(x1 + f)
    residual_ln<<<BS, 256>>>(x1, f, g2, be2, out, nullptr);
}